// round 1
// baseline (speedup 1.0000x reference)
#include <cuda_runtime.h>
#include <cuda_bf16.h>
#include <cstdint>

#define NUM_KEYS 64

// out[i] = (0 <= in[i] < 64) ? b[in[i]] : 0.0f
// Vectorized: each thread handles one int4 (4 elements) per grid-stride step.
__global__ void __launch_bounds__(256) lut_gather_kernel(
    const int4* __restrict__ in4,
    const float* __restrict__ b,
    float4* __restrict__ out4,
    int n4)
{
    __shared__ float lut[NUM_KEYS];
    if (threadIdx.x < NUM_KEYS) {
        lut[threadIdx.x] = b[threadIdx.x];
    }
    __syncthreads();

    int stride = gridDim.x * blockDim.x;
    for (int i = blockIdx.x * blockDim.x + threadIdx.x; i < n4; i += stride) {
        int4 v = in4[i];
        float4 o;
        o.x = ((unsigned)v.x < NUM_KEYS) ? lut[v.x] : 0.0f;
        o.y = ((unsigned)v.y < NUM_KEYS) ? lut[v.y] : 0.0f;
        o.z = ((unsigned)v.z < NUM_KEYS) ? lut[v.z] : 0.0f;
        o.w = ((unsigned)v.w < NUM_KEYS) ? lut[v.w] : 0.0f;
        out4[i] = o;
    }
}

extern "C" void kernel_launch(void* const* d_in, const int* in_sizes, int n_in,
                              void* d_out, int out_size) {
    // metadata order: inputs (int32, 8*4096*1024), b (float32, 64), keys (float32, 64)
    const int*   in  = (const int*)d_in[0];
    const float* b   = (const float*)d_in[1];
    float*       out = (float*)d_out;

    int n  = in_sizes[0];          // 33,554,432 — divisible by 4
    int n4 = n >> 2;               // 8,388,608 vec4 elements

    const int threads = 256;
    // ~8 elements-of-work (vec4) per thread: 148 SMs * plenty of CTAs.
    int blocks = (n4 + threads * 8 - 1) / (threads * 8);
    if (blocks < 1) blocks = 1;

    lut_gather_kernel<<<blocks, threads>>>(
        (const int4*)in, b, (float4*)out, n4);
}

// round 2
// speedup vs baseline: 1.1111x; 1.1111x over previous
#include <cuda_runtime.h>
#include <cuda_bf16.h>
#include <cstdint>

#define NUM_KEYS 64
#define THREADS 256
#define VEC_PER_THREAD 4   // 4 x int4 = 16 elements = 64B loaded + 64B stored per thread

// out[i] = (0 <= in[i] < 64) ? b[in[i]] : 0.0f
// Batched: 4 independent LDG.128 issued up front (MLP=4), then LUT, then 4 STG.128.
__global__ void __launch_bounds__(THREADS) lut_gather_kernel(
    const int4* __restrict__ in4,
    const float* __restrict__ b,
    float4* __restrict__ out4,
    int n4)
{
    __shared__ float lut[NUM_KEYS];
    if (threadIdx.x < NUM_KEYS) {
        lut[threadIdx.x] = b[threadIdx.x];
    }
    __syncthreads();

    const int block_base = blockIdx.x * (THREADS * VEC_PER_THREAD);

    int4 v[VEC_PER_THREAD];
    bool valid[VEC_PER_THREAD];

    // Front-batched independent loads (coalesced: consecutive lanes -> consecutive int4)
    #pragma unroll
    for (int j = 0; j < VEC_PER_THREAD; j++) {
        int idx = block_base + j * THREADS + threadIdx.x;
        valid[j] = (idx < n4);
        if (valid[j]) v[j] = in4[idx];
    }

    #pragma unroll
    for (int j = 0; j < VEC_PER_THREAD; j++) {
        if (!valid[j]) continue;
        float4 o;
        o.x = ((unsigned)v[j].x < NUM_KEYS) ? lut[v[j].x] : 0.0f;
        o.y = ((unsigned)v[j].y < NUM_KEYS) ? lut[v[j].y] : 0.0f;
        o.z = ((unsigned)v[j].z < NUM_KEYS) ? lut[v[j].z] : 0.0f;
        o.w = ((unsigned)v[j].w < NUM_KEYS) ? lut[v[j].w] : 0.0f;
        out4[block_base + j * THREADS + threadIdx.x] = o;
    }
}

extern "C" void kernel_launch(void* const* d_in, const int* in_sizes, int n_in,
                              void* d_out, int out_size) {
    // metadata order: inputs (int32, 8*4096*1024), b (float32, 64), keys (float32, 64)
    const int*   in  = (const int*)d_in[0];
    const float* b   = (const float*)d_in[1];
    float*       out = (float*)d_out;

    int n  = in_sizes[0];          // 33,554,432 — divisible by 16
    int n4 = n >> 2;               // 8,388,608 int4 elements

    const int per_block = THREADS * VEC_PER_THREAD;      // 1024 int4 per block
    int blocks = (n4 + per_block - 1) / per_block;        // 8192 for the bench shape

    lut_gather_kernel<<<blocks, THREADS>>>(
        (const int4*)in, b, (float4*)out, n4);
}